// round 15
// baseline (speedup 1.0000x reference)
#include <cuda_runtime.h>
#include <cstdint>

// Sinkhorn on B x 64 x 64 matrices, scaling-vector form, one warp per matrix,
// one 32-thread CTA per matrix. K frozen in registers, ROW-PAIR packed:
// K2[k][j] = (row 2k', row 2k'+1) of local col j  (k' = k^tj, local col j has
// XOR-permuted pack mapping). Row matvec needs no horizontal sums; col matvec
// consumes allgathered rv in packed form. Uniform select-free reduce-scatters
// (R13/R14 algebra), smem-staged coalesced I/O (R14).

typedef unsigned long long u64;
#define FULLMASK 0xffffffffu

__device__ __forceinline__ u64 pk2(float lo, float hi){
    u64 r; asm("mov.b64 %0, {%1, %2};" : "=l"(r) : "f"(lo), "f"(hi)); return r;
}
__device__ __forceinline__ void up2(u64 p, float& lo, float& hi){
    asm("mov.b64 {%0, %1}, %2;" : "=f"(lo), "=f"(hi) : "l"(p));
}
__device__ __forceinline__ u64 addx2(u64 a, u64 b){
    u64 r; asm("add.rn.f32x2 %0, %1, %2;" : "=l"(r) : "l"(a), "l"(b)); return r;
}
__device__ __forceinline__ u64 mulx2(u64 a, u64 b){
    u64 r; asm("mul.rn.f32x2 %0, %1, %2;" : "=l"(r) : "l"(a), "l"(b)); return r;
}
__device__ __forceinline__ u64 fmax2(u64 a, u64 b, u64 c){
    u64 r; asm("fma.rn.f32x2 %0, %1, %2, %3;" : "=l"(r) : "l"(a), "l"(b), "l"(c)); return r;
}
__device__ __forceinline__ float frcp(float x){
    float r; asm("rcp.approx.f32 %0, %1;" : "=f"(r) : "f"(x)); return r;
}
__device__ __forceinline__ float fex2(float x){
    float r; asm("ex2.approx.f32 %0, %1;" : "=f"(r) : "f"(x)); return r;
}
__device__ __forceinline__ u64 shfl64(u64 v, int m){
    return __shfl_xor_sync(FULLMASK, v, m);
}
__device__ __forceinline__ u64 max2u(u64 A, u64 B){
    float a, b, c, d; up2(A, a, b); up2(B, c, d);
    return pk2(fmaxf(a, c), fmaxf(b, d));
}

// Pre-permuted, lane-interleaved softplus(-gamma)*10*log2(e) table.
// Entry [e*32 + lane], e = 4k + 2s + which: 4 gamma values for row (k,s) of
// lane, local cols 4*which .. 4*which+3 (local-pack order with f baked in).
__device__ float4 d_gtab[1024];

__global__ void prep_kernel(const float* __restrict__ gamma){
    int t = blockIdx.x * blockDim.x + threadIdx.x;
    if (t < 1024){
        int lane = t & 31, e = t >> 5;
        int k = e >> 2, s = (e >> 1) & 1, which = e & 1;
        int tj = lane & 7, ti = lane >> 3;
        int f = ((ti & 1) << 1) | (ti >> 1);       // 2-bit reverse of ti
        int rg = 16 * ti + 2 * (k ^ tj) + s;        // global row
        int base = 8 * tj;
        int p0 = (2 * which) ^ f, p1 = (2 * which + 1) ^ f;  // global packs
        int c0 = base + 2 * p0, c1 = base + 2 * p1;
        const float KS = 14.4269504088896341f;
        float g;
        float4 o;
        g = gamma[rg * 64 + c0];
        o.x = ((g > 0.f) ? log1pf(expf(-g)) : (-g + log1pf(expf(g)))) * KS;
        g = gamma[rg * 64 + c0 + 1];
        o.y = ((g > 0.f) ? log1pf(expf(-g)) : (-g + log1pf(expf(g)))) * KS;
        g = gamma[rg * 64 + c1];
        o.z = ((g > 0.f) ? log1pf(expf(-g)) : (-g + log1pf(expf(g)))) * KS;
        g = gamma[rg * 64 + c1 + 1];
        o.w = ((g > 0.f) ? log1pf(expf(-g)) : (-g + log1pf(expf(g)))) * KS;
        d_gtab[t] = o;
    }
}

__global__ void __launch_bounds__(32, 12) sinkhorn_kernel(
        const float* __restrict__ noise, float* __restrict__ out){
    // Staging tile in GLOBAL element order, column-float4 swizzled by row pair:
    // element (rg, c4) lives at tile[rg*16 + ((c4 + ((rg>>1)&7)) & 15)].
    __shared__ float4 tile[1024];                 // 16 KB

    int gw = blockIdx.x;                          // matrix id (grid = B)
    int lane = threadIdx.x;
    int tj = lane & 7;
    int ti = lane >> 3;
    int f = ((ti & 1) << 1) | (ti >> 1);          // 2-bit reverse of ti
    int w = f >> 1;                               // = ti & 1
    bool s1 = (f & 1) != 0;                       // = ti >> 1
    const float KS = 14.4269504088896341f;        // 10 * log2(e)
    int c4a = 2 * tj + w, c4b = 2 * tj + 1 - w;

    // ---- stage noise: linear coalesced loads -> swizzled smem ----
    const float4* nb = (const float4*)(noise + (size_t)gw * 4096);
    #pragma unroll
    for (int c = 0; c < 32; ++c){
        int idx = c * 32 + lane;
        int rg = idx >> 4, c4 = idx & 15;
        tile[rg * 16 + ((c4 + ((rg >> 1) & 7)) & 15)] = nb[idx];
    }
    __syncwarp();

    // K2[k][j]: packed (row 2(k^tj), row 2(k^tj)+1) of local col j.
    u64 K2[8][8];
    u64 xmp[8];                                   // packed per-row-pair maxes

    #pragma unroll
    for (int k = 0; k < 8; ++k){
        int pg = k ^ tj;
        float xs[2][8];
        #pragma unroll
        for (int s = 0; s < 2; ++s){
            int rg = 16 * ti + 2 * pg + s;
            float4 nA = tile[rg * 16 + ((c4a + pg) & 15)];
            float4 nB = tile[rg * 16 + ((c4b + pg) & 15)];
            int e = 4 * k + 2 * s;
            float4 gA = d_gtab[e * 32 + lane];
            float4 gB = d_gtab[(e + 1) * 32 + lane];
            float na0 = s1 ? nA.z : nA.x, na1 = s1 ? nA.w : nA.y;
            float na2 = s1 ? nA.x : nA.z, na3 = s1 ? nA.y : nA.w;
            float nb0 = s1 ? nB.z : nB.x, nb1 = s1 ? nB.w : nB.y;
            float nb2 = s1 ? nB.x : nB.z, nb3 = s1 ? nB.y : nB.w;
            xs[s][0] = fmaf(na0, KS, gA.x);
            xs[s][1] = fmaf(na1, KS, gA.y);
            xs[s][2] = fmaf(na2, KS, gA.z);
            xs[s][3] = fmaf(na3, KS, gA.w);
            xs[s][4] = fmaf(nb0, KS, gB.x);
            xs[s][5] = fmaf(nb1, KS, gB.y);
            xs[s][6] = fmaf(nb2, KS, gB.z);
            xs[s][7] = fmaf(nb3, KS, gB.w);
        }
        #pragma unroll
        for (int j = 0; j < 8; ++j) K2[k][j] = pk2(xs[0][j], xs[1][j]);
        float m0 = fmaxf(fmaxf(fmaxf(xs[0][0], xs[0][1]), fmaxf(xs[0][2], xs[0][3])),
                         fmaxf(fmaxf(xs[0][4], xs[0][5]), fmaxf(xs[0][6], xs[0][7])));
        float m1 = fmaxf(fmaxf(fmaxf(xs[1][0], xs[1][1]), fmaxf(xs[1][2], xs[1][3])),
                         fmaxf(fmaxf(xs[1][4], xs[1][5]), fmaxf(xs[1][6], xs[1][7])));
        xmp[k] = pk2(m0, m1);
    }
    // ---- row-max: uniform packed max reduce-scatter over tj + xor allgather,
    //      then aligned packed subtract + exp2 ----
    {
        #pragma unroll
        for (int k = 0; k < 4; ++k) xmp[k] = max2u(xmp[k], shfl64(xmp[k + 4], 4));
        #pragma unroll
        for (int k = 0; k < 2; ++k) xmp[k] = max2u(xmp[k], shfl64(xmp[k + 2], 2));
        xmp[0] = max2u(xmp[0], shfl64(xmp[1], 1));
        #pragma unroll
        for (int k = 0; k < 8; ++k){
            u64 mk = k ? shfl64(xmp[0], k) : xmp[0];
            float ml, mh; up2(mk, ml, mh);
            u64 nm = pk2(-ml, -mh);               // aligned with row-pair packing
            #pragma unroll
            for (int j = 0; j < 8; ++j){
                u64 t = addx2(K2[k][j], nm);
                float u, v; up2(t, u, v);
                K2[k][j] = pk2(fex2(u), fex2(v));
            }
        }
    }

    // Iteration state: cb2[j] = (c_localcol_j, same) broadcast; rv2[k] = packed
    // reciprocal row sums for local pair k.
    u64 cb2[8];
    #pragma unroll
    for (int j = 0; j < 8; ++j) cb2[j] = pk2(1.f, 1.f);
    u64 rv2[8];

    #pragma unroll 1
    for (int it = 0; it < 50; ++it){
        // ---- row matvec: packed row-pair sums directly, no horizontal ----
        u64 pr[8];
        #pragma unroll
        for (int k = 0; k < 8; ++k){
            u64 acc = mulx2(K2[k][0], cb2[0]);
            #pragma unroll
            for (int j = 1; j < 8; ++j) acc = fmax2(K2[k][j], cb2[j], acc);
            pr[k] = acc;
        }
        // ---- UNIFORM reduce-scatter over tj ----
        #pragma unroll
        for (int k = 0; k < 4; ++k) pr[k] = addx2(pr[k], shfl64(pr[k + 4], 4));
        #pragma unroll
        for (int k = 0; k < 2; ++k) pr[k] = addx2(pr[k], shfl64(pr[k + 2], 2));
        pr[0] = addx2(pr[0], shfl64(pr[1], 1));
        u64 own_rv;
        { float u, v; up2(pr[0], u, v); own_rv = pk2(frcp(u), frcp(v)); }
        // ---- allgather: owner of local pair k is lane^k ----
        rv2[0] = own_rv;
        #pragma unroll
        for (int k = 1; k < 8; ++k) rv2[k] = shfl64(own_rv, k);

        // ---- col matvec: 8 independent chains, rv consumed packed ----
        u64 ac[8];
        #pragma unroll
        for (int j = 0; j < 8; ++j) ac[j] = mulx2(K2[0][j], rv2[0]);
        #pragma unroll
        for (int k = 1; k < 8; ++k){
            #pragma unroll
            for (int j = 0; j < 8; ++j) ac[j] = fmax2(K2[k][j], rv2[k], ac[j]);
        }
        // horizontal over the row pair + pack into local col packs
        float cs[8];
        #pragma unroll
        for (int j = 0; j < 8; ++j){
            float u, v; up2(ac[j], u, v);
            cs[j] = u + v;
        }
        u64 cp[4];
        cp[0] = pk2(cs[0], cs[1]);
        cp[1] = pk2(cs[2], cs[3]);
        cp[2] = pk2(cs[4], cs[5]);
        cp[3] = pk2(cs[6], cs[7]);
        // ---- UNIFORM reduce-scatter over ti (xor8 then xor16) ----
        cp[0] = addx2(cp[0], shfl64(cp[2], 8));
        cp[1] = addx2(cp[1], shfl64(cp[3], 8));
        cp[0] = addx2(cp[0], shfl64(cp[1], 16));
        float u, v; up2(cp[0], u, v);
        u64 own_c = pk2(frcp(u), frcp(v));
        // ---- allgather + unpack to broadcasts ----
        u64 q0 = own_c;
        u64 q1 = shfl64(own_c, 16);
        u64 q2 = shfl64(own_c, 8);
        u64 q3 = shfl64(own_c, 24);
        float a, b;
        up2(q0, a, b); cb2[0] = pk2(a, a); cb2[1] = pk2(b, b);
        up2(q1, a, b); cb2[2] = pk2(a, a); cb2[3] = pk2(b, b);
        up2(q2, a, b); cb2[4] = pk2(a, a); cb2[5] = pk2(b, b);
        up2(q3, a, b); cb2[6] = pk2(a, a); cb2[7] = pk2(b, b);
    }

    // ---- materialize out = diag(r) K diag(c): unpack row pairs, stage through
    //      swizzled smem, then linear coalesced stores ----
    __syncwarp();
    #pragma unroll
    for (int k = 0; k < 8; ++k){
        int pg = k ^ tj;
        float a[8], b[8];
        #pragma unroll
        for (int j = 0; j < 8; ++j){
            u64 t = mulx2(mulx2(K2[k][j], rv2[k]), cb2[j]);
            up2(t, a[j], b[j]);
        }
        int rg = 16 * ti + 2 * pg;
        // row s=0
        tile[rg * 16 + ((c4a + pg) & 15)] =
            s1 ? make_float4(a[2], a[3], a[0], a[1])
               : make_float4(a[0], a[1], a[2], a[3]);
        tile[rg * 16 + ((c4b + pg) & 15)] =
            s1 ? make_float4(a[6], a[7], a[4], a[5])
               : make_float4(a[4], a[5], a[6], a[7]);
        // row s=1
        tile[(rg + 1) * 16 + ((c4a + pg) & 15)] =
            s1 ? make_float4(b[2], b[3], b[0], b[1])
               : make_float4(b[0], b[1], b[2], b[3]);
        tile[(rg + 1) * 16 + ((c4b + pg) & 15)] =
            s1 ? make_float4(b[6], b[7], b[4], b[5])
               : make_float4(b[4], b[5], b[6], b[7]);
    }
    __syncwarp();
    float4* ob = (float4*)(out + (size_t)gw * 4096);
    #pragma unroll
    for (int c = 0; c < 32; ++c){
        int idx = c * 32 + lane;
        int rg = idx >> 4, c4 = idx & 15;
        ob[idx] = tile[rg * 16 + ((c4 + ((rg >> 1) & 7)) & 15)];
    }
}

extern "C" void kernel_launch(void* const* d_in, const int* in_sizes, int n_in,
                              void* d_out, int out_size) {
    const float* gamma = (const float*)d_in[0];   // [64,64] fp32
    const float* noise = (const float*)d_in[1];   // [B,64,64] fp32
    float* out = (float*)d_out;                   // [B,64,64] fp32
    int B = in_sizes[1] / (64 * 64);

    prep_kernel<<<4, 256>>>(gamma);
    sinkhorn_kernel<<<B, 32>>>(noise, out);       // one 32-thread CTA per matrix
}